// round 8
// baseline (speedup 1.0000x reference)
#include <cuda_runtime.h>
#include <cuda_fp16.h>
#include <math_constants.h>

#define VOCAB    100000
#define RAND_DIM 100
#define WAE      50
#define CLS      4
#define VDIM     100
#define NPATH    16384
#define PLEN     50
#define HDIM     150     // RAND_DIM + WAE
#define PADT     208     // table row pitch in halves: 416 B, 26 uint4, 52 ull
#define NBLK     (NPATH / 8)
#define WPITCH   52      // swT row pitch in ulls (50 used)

typedef unsigned long long ull;

// Fused gather table: row v = [fp16 E_td[v][0:100] | fp16 E_wae[v][0:100] | pad]
__device__ __half g_T[(size_t)VOCAB * PADT];   // ~41.6 MB
__device__ float  g_max[HDIM];
__device__ int    g_done;

// ---------------------------------------------------------------------------
__device__ __forceinline__ ull fma2(ull a, ull b, ull c) {
    ull d;
    asm("fma.rn.f32x2 %0, %1, %2, %3;" : "=l"(d) : "l"(a), "l"(b), "l"(c));
    return d;
}
__device__ __forceinline__ void unpack2(ull v, float& lo, float& hi) {
    asm("mov.b64 {%0, %1}, %2;" : "=f"(lo), "=f"(hi) : "l"(v));
}
__device__ __forceinline__ ull packf2(float lo, float hi) {
    ull d;
    asm("mov.b64 %0, {%1, %2};" : "=l"(d) : "f"(lo), "f"(hi));
    return d;
}
__device__ __forceinline__ __half2 asH2(unsigned u) {
    return *reinterpret_cast<__half2*>(&u);
}
__device__ __forceinline__ void atomicMaxF(float* addr, float v) {
    if (v >= 0.f) atomicMax((int*)addr, __float_as_int(v));
    else          atomicMin((unsigned int*)addr, __float_as_uint(v));
}
__device__ __forceinline__ ull packh(float a, float b, float c, float d) {
    __half2 h0 = __floats2half2_rn(a, b);
    __half2 h1 = __floats2half2_rn(c, d);
    unsigned lo = *reinterpret_cast<unsigned*>(&h0);
    unsigned hi = *reinterpret_cast<unsigned*>(&h1);
    return (ull)lo | ((ull)hi << 32);
}
__device__ __forceinline__ uint4 ldcg4(const uint4* p) {
    uint4 v;
    asm volatile("ld.global.cg.v4.u32 {%0,%1,%2,%3}, [%4];"
                 : "=r"(v.x), "=r"(v.y), "=r"(v.z), "=r"(v.w) : "l"(p));
    return v;
}

// ---------------------------------------------------------------------------
// Kernel 1: streaming fp32 -> fp16 table build. A and B processed in one
// loop: 2 independent loads in flight, index math amortized.
// ---------------------------------------------------------------------------
__global__ void __launch_bounds__(256)
convert_kernel(const float* __restrict__ E_td,
               const float* __restrict__ E_wae) {
    if (blockIdx.x == 0) {
        if (threadIdx.x < HDIM) g_max[threadIdx.x] = -CUDART_INF_F;
        if (threadIdx.x == 0)   g_done = 0;
    }

    const float4* A = (const float4*)E_td;    // 25 float4 per row
    const float4* B = (const float4*)E_wae;   // 25 float4 per row
    ull* T = (ull*)g_T;                       // 52 ull per row (50 written)

    const size_t N = (size_t)VOCAB * 25;
    size_t stride = (size_t)gridDim.x * blockDim.x;

    for (size_t i = (size_t)blockIdx.x * blockDim.x + threadIdx.x;
         i < N; i += stride) {
        float4 va = __ldcs(&A[i]);
        float4 vb = __ldcs(&B[i]);
        size_t row = i / 25, j = i % 25;
        T[row * 52 + j]      = packh(va.x, va.y, va.z, va.w);
        T[row * 52 + 25 + j] = packh(vb.x, vb.y, vb.z, vb.w);
    }
}

// ---------------------------------------------------------------------------
// Kernel 2: gather + per-path WAE linear + activations + max-pool + fused
// finalize. One warp per path, lanes 0..24 own 16B chunks (dims 8l..8l+7).
// 5 tokens per body, full fp16 tree (one f32 convert per body per half2).
// Linear uses dup-free f32x2 FMAs: swT[kp][c] = (W[2kp][c], W[2kp+1][c])
// pairs with contiguous bow pairs; lo+hi horizontal add at the end.
// ---------------------------------------------------------------------------
__global__ void __launch_bounds__(256)
path_gather_kernel(const int*   __restrict__ x,
                   const float* __restrict__ W_enc,
                   const float* __restrict__ b_enc,
                   const float* __restrict__ w_out,
                   const float* __restrict__ b_out,
                   const int*   __restrict__ y,
                   float* __restrict__ out, int out_size) {
    __shared__ float smax[HDIM];
    __shared__ ull   swT[50 * WPITCH];   // [kp][c] k-pair packed W   20.8 KB
    __shared__ float sbow[8][VDIM];      // per-warp bag-of-words      3.2 KB
    __shared__ int   s_last;

    int tid = threadIdx.x;
    for (int i = tid; i < HDIM; i += 256) smax[i] = -CUDART_INF_F;
    // swT[kp*WPITCH + c] = (W[2kp][c], W[2kp+1][c]); reads coalesced over c
    for (int i = tid; i < 50 * 50; i += 256) {
        int kp = i / 50, c = i % 50;
        swT[kp * WPITCH + c] = packf2(__ldg(&W_enc[(2 * kp) * 50 + c]),
                                      __ldg(&W_enc[(2 * kp + 1) * 50 + c]));
    }
    __syncthreads();

    int w = tid >> 5, lane = tid & 31;
    int p = blockIdx.x * 8 + w;
    const int* xp = x + (size_t)p * PLEN;

    int tA = xp[lane];
    int tB = (lane < PLEN - 32) ? xp[32 + lane] : 0;

    bool act = lane < 25;
    const uint4* T4 = (const uint4*)g_T + lane;   // per-lane chunk base, 26/row

    float2 a0 = {0.f, 0.f}, a1 = {0.f, 0.f}, a2 = {0.f, 0.f}, a3 = {0.f, 0.f};

    #pragma unroll
    for (int t = 0; t < PLEN; t += 5) {
        int k0 = (t     < 32) ? __shfl_sync(0xffffffffu, tA, t)     : __shfl_sync(0xffffffffu, tB, t - 32);
        int k1 = (t + 1 < 32) ? __shfl_sync(0xffffffffu, tA, t + 1) : __shfl_sync(0xffffffffu, tB, t - 31);
        int k2 = (t + 2 < 32) ? __shfl_sync(0xffffffffu, tA, t + 2) : __shfl_sync(0xffffffffu, tB, t - 30);
        int k3 = (t + 3 < 32) ? __shfl_sync(0xffffffffu, tA, t + 3) : __shfl_sync(0xffffffffu, tB, t - 29);
        int k4 = (t + 4 < 32) ? __shfl_sync(0xffffffffu, tA, t + 4) : __shfl_sync(0xffffffffu, tB, t - 28);
        if (act) {
            uint4 v0 = ldcg4(T4 + (size_t)k0 * 26);
            uint4 v1 = ldcg4(T4 + (size_t)k1 * 26);
            uint4 v2 = ldcg4(T4 + (size_t)k2 * 26);
            uint4 v3 = ldcg4(T4 + (size_t)k3 * 26);
            uint4 v4 = ldcg4(T4 + (size_t)k4 * 26);
            __half2 s0 = __hadd2(__hadd2(__hadd2(asH2(v0.x), asH2(v1.x)),
                                         __hadd2(asH2(v2.x), asH2(v3.x))), asH2(v4.x));
            __half2 s1 = __hadd2(__hadd2(__hadd2(asH2(v0.y), asH2(v1.y)),
                                         __hadd2(asH2(v2.y), asH2(v3.y))), asH2(v4.y));
            __half2 s2 = __hadd2(__hadd2(__hadd2(asH2(v0.z), asH2(v1.z)),
                                         __hadd2(asH2(v2.z), asH2(v3.z))), asH2(v4.z));
            __half2 s3 = __hadd2(__hadd2(__hadd2(asH2(v0.w), asH2(v1.w)),
                                         __hadd2(asH2(v2.w), asH2(v3.w))), asH2(v4.w));
            float2 f;
            f = __half22float2(s0); a0.x += f.x; a0.y += f.y;
            f = __half22float2(s1); a1.x += f.x; a1.y += f.y;
            f = __half22float2(s2); a2.x += f.x; a2.y += f.y;
            f = __half22float2(s3); a3.x += f.x; a3.y += f.y;
        }
    }

    if (act) {
        float f[8] = {a0.x, a0.y, a1.x, a1.y, a2.x, a2.y, a3.x, a3.y};
        int d0 = lane * 8;
        #pragma unroll
        for (int j = 0; j < 8; j++) {
            int d = d0 + j;
            if (d < RAND_DIM) {
                float v = f[j];
                v = (v > 0.f) ? v : 0.01f * v;       // leaky_relu
                atomicMaxF(&smax[d], v);
            } else {
                sbow[w][d - RAND_DIM] = f[j];        // bow dims 0..99
            }
        }
    }
    __syncwarp();

    if (act) {   // per-path linear 100x50, dup-free f32x2
        ull accA = 0ull, accB = 0ull;
        const ull* bwp = (const ull*)sbow[w];        // (bw[2kp], bw[2kp+1])
        int c0 = 2 * lane;
        #pragma unroll 10
        for (int kp = 0; kp < 50; kp++) {
            ull b2 = bwp[kp];
            accA = fma2(b2, swT[kp * WPITCH + c0],     accA);
            accB = fma2(b2, swT[kp * WPITCH + c0 + 1], accB);
        }
        float lo, hi;
        unpack2(accA, lo, hi);
        float r0 = lo + hi;
        unpack2(accB, lo, hi);
        float r1 = lo + hi;
        float v0 = fmaxf(r0 + __ldg(&b_enc[c0]),     0.f);   // relu
        float v1 = fmaxf(r1 + __ldg(&b_enc[c0 + 1]), 0.f);
        atomicMaxF(&smax[RAND_DIM + c0],     v0);
        atomicMaxF(&smax[RAND_DIM + c0 + 1], v1);
    }
    __syncthreads();

    for (int i = tid; i < HDIM; i += 256) atomicMaxF(&g_max[i], smax[i]);

    // ---- fused finalize ----
    __threadfence();
    if (tid == 0) s_last = (atomicAdd(&g_done, 1) == NBLK - 1);
    __syncthreads();
    if (!s_last || w != 0) return;

    float part[CLS] = {0.f, 0.f, 0.f, 0.f};
    for (int d = lane; d < HDIM; d += 32) {
        float m = __ldcg(&g_max[d]);
        #pragma unroll
        for (int c = 0; c < CLS; c++)
            part[c] = fmaf(w_out[c * HDIM + d], m, part[c]);
    }
    #pragma unroll
    for (int off = 16; off > 0; off >>= 1) {
        #pragma unroll
        for (int c = 0; c < CLS; c++)
            part[c] += __shfl_down_sync(0xffffffffu, part[c], off);
    }
    if (lane == 0) {
        float logits[CLS], prob[CLS];
        float mx = -CUDART_INF_F;
        #pragma unroll
        for (int c = 0; c < CLS; c++) {
            logits[c] = part[c] + b_out[c];
            mx = fmaxf(mx, logits[c]);
        }
        float s = 0.f;
        #pragma unroll
        for (int c = 0; c < CLS; c++) { prob[c] = expf(logits[c] - mx); s += prob[c]; }
        #pragma unroll
        for (int c = 0; c < CLS; c++) prob[c] /= s;

        int label = 0, best = y[0];
        #pragma unroll
        for (int c = 1; c < CLS; c++) if (y[c] > best) { best = y[c]; label = c; }

        float mx2 = prob[0];
        #pragma unroll
        for (int c = 1; c < CLS; c++) mx2 = fmaxf(mx2, prob[c]);
        float s2 = 0.f;
        #pragma unroll
        for (int c = 0; c < CLS; c++) s2 += expf(prob[c] - mx2);
        float loss = -(prob[label] - (mx2 + logf(s2)));

        for (int c = 0; c < CLS && c < out_size; c++) out[c] = prob[c];
        if (out_size > CLS) out[CLS] = loss;
    }
}

// ---------------------------------------------------------------------------
extern "C" void kernel_launch(void* const* d_in, const int* in_sizes, int n_in,
                              void* d_out, int out_size) {
    const int*   x     = (const int*)  d_in[0];
    const int*   y     = (const int*)  d_in[1];
    const float* E_td  = (const float*)d_in[2];
    const float* E_wae = (const float*)d_in[3];
    const float* W_enc = (const float*)d_in[4];
    const float* b_enc = (const float*)d_in[5];
    const float* w_out = (const float*)d_in[6];
    const float* b_out = (const float*)d_in[7];
    float* out = (float*)d_out;

    convert_kernel<<<1184, 256>>>(E_td, E_wae);
    path_gather_kernel<<<NBLK, 256>>>(x, W_enc, b_enc, w_out, b_out, y,
                                      out, out_size);
}

// round 10
// speedup vs baseline: 1.1560x; 1.1560x over previous
#include <cuda_runtime.h>
#include <cuda_fp16.h>
#include <math_constants.h>

#define VOCAB    100000
#define RAND_DIM 100
#define WAE      50
#define CLS      4
#define VDIM     100
#define NPATH    16384
#define PLEN     50
#define HDIM     150     // RAND_DIM + WAE
#define PADT     208     // table row pitch in halves: 416 B, 26 uint4
#define NBLK     (NPATH / 8)

typedef unsigned long long ull;

// Fused gather table: row v = [fp16 E_td[v][0:100] | fp16 E_wae[v][0:100] | pad]
__device__ __half  g_T[(size_t)VOCAB * PADT];   // ~41.6 MB
__device__ float4  g_bow[(size_t)NPATH * 25];   // per-path bag-of-words, 6.5 MB
__device__ float   g_max[HDIM];
__device__ int     g_done;

// ---------------------------------------------------------------------------
__device__ __forceinline__ ull fma2(ull a, ull b, ull c) {
    ull d;
    asm("fma.rn.f32x2 %0, %1, %2, %3;" : "=l"(d) : "l"(a), "l"(b), "l"(c));
    return d;
}
__device__ __forceinline__ ull dup2(float v) {
    ull d;
    asm("mov.b64 %0, {%1, %1};" : "=l"(d) : "f"(v));
    return d;
}
__device__ __forceinline__ void unpack2(ull v, float& lo, float& hi) {
    asm("mov.b64 {%0, %1}, %2;" : "=f"(lo), "=f"(hi) : "l"(v));
}
__device__ __forceinline__ __half2 asH2(unsigned u) {
    return *reinterpret_cast<__half2*>(&u);
}
__device__ __forceinline__ void atomicMaxF(float* addr, float v) {
    if (v >= 0.f) atomicMax((int*)addr, __float_as_int(v));
    else          atomicMin((unsigned int*)addr, __float_as_uint(v));
}
__device__ __forceinline__ ull packh(float a, float b, float c, float d) {
    __half2 h0 = __floats2half2_rn(a, b);
    __half2 h1 = __floats2half2_rn(c, d);
    unsigned lo = *reinterpret_cast<unsigned*>(&h0);
    unsigned hi = *reinterpret_cast<unsigned*>(&h1);
    return (ull)lo | ((ull)hi << 32);
}
__device__ __forceinline__ uint4 ldcg4(const uint4* p) {
    uint4 v;
    asm volatile("ld.global.cg.v4.u32 {%0,%1,%2,%3}, [%4];"
                 : "=r"(v.x), "=r"(v.y), "=r"(v.z), "=r"(v.w) : "l"(p));
    return v;
}
__device__ __forceinline__ void stcg4(float4* p, float4 v) {
    asm volatile("st.global.cg.v4.f32 [%0], {%1,%2,%3,%4};"
                 :: "l"(p), "f"(v.x), "f"(v.y), "f"(v.z), "f"(v.w));
}

// ---------------------------------------------------------------------------
// Kernel 1: streaming fp32 -> fp16 table build.
// ---------------------------------------------------------------------------
__global__ void __launch_bounds__(256)
convert_kernel(const float* __restrict__ E_td,
               const float* __restrict__ E_wae) {
    if (blockIdx.x == 0) {
        if (threadIdx.x < HDIM) g_max[threadIdx.x] = -CUDART_INF_F;
        if (threadIdx.x == 0)   g_done = 0;
    }

    const float4* A = (const float4*)E_td;    // 25 float4 per row
    const float4* B = (const float4*)E_wae;   // 25 float4 per row
    ull* T = (ull*)g_T;                       // 52 ull per row

    const size_t N = (size_t)VOCAB * 25;
    size_t stride = (size_t)gridDim.x * blockDim.x;

    for (size_t i = (size_t)blockIdx.x * blockDim.x + threadIdx.x;
         i < N; i += stride) {
        float4 va = __ldcs(&A[i]);
        float4 vb = __ldcs(&B[i]);
        size_t row = i / 25, j = i % 25;
        T[row * 52 + j]      = packh(va.x, va.y, va.z, va.w);
        T[row * 52 + 25 + j] = packh(vb.x, vb.y, vb.z, vb.w);
    }
}

// ---------------------------------------------------------------------------
// Kernel 2: pure gather. One warp per path, lanes 0..24 own 16B chunks
// (dims 8l..8l+7). 4 tokens + tail, ldcg, fp16 tree.
// Dims 0..99 -> leaky_relu + block max. Dims 100..199 (bow) -> g_bow.
// ---------------------------------------------------------------------------
__global__ void __launch_bounds__(256)
path_gather_kernel(const int* __restrict__ x) {
    __shared__ float smax[RAND_DIM];
    int tid = threadIdx.x;
    if (tid < RAND_DIM) smax[tid] = -CUDART_INF_F;
    __syncthreads();

    int w = tid >> 5, lane = tid & 31;
    int p = blockIdx.x * 8 + w;
    const int* xp = x + (size_t)p * PLEN;

    int tA = xp[lane];
    int tB = (lane < PLEN - 32) ? xp[32 + lane] : 0;

    bool act = lane < 25;
    const uint4* T4 = (const uint4*)g_T + lane;   // per-lane chunk base, 26/row

    float2 a0 = {0.f, 0.f}, a1 = {0.f, 0.f}, a2 = {0.f, 0.f}, a3 = {0.f, 0.f};

    #pragma unroll
    for (int t = 0; t < 48; t += 4) {
        int k0 = (t     < 32) ? __shfl_sync(0xffffffffu, tA, t)     : __shfl_sync(0xffffffffu, tB, t - 32);
        int k1 = (t + 1 < 32) ? __shfl_sync(0xffffffffu, tA, t + 1) : __shfl_sync(0xffffffffu, tB, t - 31);
        int k2 = (t + 2 < 32) ? __shfl_sync(0xffffffffu, tA, t + 2) : __shfl_sync(0xffffffffu, tB, t - 30);
        int k3 = (t + 3 < 32) ? __shfl_sync(0xffffffffu, tA, t + 3) : __shfl_sync(0xffffffffu, tB, t - 29);
        if (act) {
            uint4 v0 = ldcg4(T4 + (size_t)k0 * 26);
            uint4 v1 = ldcg4(T4 + (size_t)k1 * 26);
            uint4 v2 = ldcg4(T4 + (size_t)k2 * 26);
            uint4 v3 = ldcg4(T4 + (size_t)k3 * 26);
            __half2 s0 = __hadd2(__hadd2(asH2(v0.x), asH2(v1.x)), __hadd2(asH2(v2.x), asH2(v3.x)));
            __half2 s1 = __hadd2(__hadd2(asH2(v0.y), asH2(v1.y)), __hadd2(asH2(v2.y), asH2(v3.y)));
            __half2 s2 = __hadd2(__hadd2(asH2(v0.z), asH2(v1.z)), __hadd2(asH2(v2.z), asH2(v3.z)));
            __half2 s3 = __hadd2(__hadd2(asH2(v0.w), asH2(v1.w)), __hadd2(asH2(v2.w), asH2(v3.w)));
            float2 f;
            f = __half22float2(s0); a0.x += f.x; a0.y += f.y;
            f = __half22float2(s1); a1.x += f.x; a1.y += f.y;
            f = __half22float2(s2); a2.x += f.x; a2.y += f.y;
            f = __half22float2(s3); a3.x += f.x; a3.y += f.y;
        }
    }
    {   // tail: tokens 48, 49
        int k0 = __shfl_sync(0xffffffffu, tB, 16);
        int k1 = __shfl_sync(0xffffffffu, tB, 17);
        if (act) {
            uint4 v0 = ldcg4(T4 + (size_t)k0 * 26);
            uint4 v1 = ldcg4(T4 + (size_t)k1 * 26);
            __half2 s0 = __hadd2(asH2(v0.x), asH2(v1.x));
            __half2 s1 = __hadd2(asH2(v0.y), asH2(v1.y));
            __half2 s2 = __hadd2(asH2(v0.z), asH2(v1.z));
            __half2 s3 = __hadd2(asH2(v0.w), asH2(v1.w));
            float2 f;
            f = __half22float2(s0); a0.x += f.x; a0.y += f.y;
            f = __half22float2(s1); a1.x += f.x; a1.y += f.y;
            f = __half22float2(s2); a2.x += f.x; a2.y += f.y;
            f = __half22float2(s3); a3.x += f.x; a3.y += f.y;
        }
    }

    if (act) {
        float f[8] = {a0.x, a0.y, a1.x, a1.y, a2.x, a2.y, a3.x, a3.y};
        int d0 = lane * 8;
        // dims < 100: leaky_relu + max
        #pragma unroll
        for (int j = 0; j < 8; j++) {
            int d = d0 + j;
            if (d < RAND_DIM) {
                float v = f[j];
                v = (v > 0.f) ? v : 0.01f * v;
                atomicMaxF(&smax[d], v);
            }
        }
        // bow dims (>= 100): write to scratch. lane 12 owns bow[0..3]
        // (its dims 100..103 sit in f[4..7]); lanes 13..24 own bow chunks
        // 2l-25 (f[0..3]) and 2l-24 (f[4..7]).
        float4* bp = g_bow + (size_t)p * 25;
        if (lane == 12) {
            stcg4(bp, make_float4(f[4], f[5], f[6], f[7]));
        } else if (lane >= 13) {
            stcg4(bp + (2 * lane - 25), make_float4(f[0], f[1], f[2], f[3]));
            stcg4(bp + (2 * lane - 24), make_float4(f[4], f[5], f[6], f[7]));
        }
    }
    __syncthreads();

    if (tid < RAND_DIM) atomicMaxF(&g_max[tid], smax[tid]);
}

// ---------------------------------------------------------------------------
// Kernel 3: per-path 100x50 linear + relu + max, fused finalize in last
// block. sbow4 is float4 (16B-aligned) — the R9 crash was a float4 store
// into a 4B-aligned float array.
// ---------------------------------------------------------------------------
__global__ void __launch_bounds__(256)
bow_linear_kernel(const float* __restrict__ W_enc,
                  const float* __restrict__ b_enc,
                  const float* __restrict__ w_out,
                  const float* __restrict__ b_out,
                  const int*   __restrict__ y,
                  float* __restrict__ out, int out_size) {
    __shared__ float  smax[WAE];
    __shared__ ull    sW2[VDIM * 25];     // W_enc col-pairs  20 KB
    __shared__ float4 sbow4[8][25];       // 16B-aligned per-warp bow
    __shared__ int    s_last;

    int tid = threadIdx.x;
    if (tid < WAE) smax[tid] = -CUDART_INF_F;
    {
        const ull* Ws = (const ull*)W_enc;
        for (int i = tid; i < VDIM * 25; i += 256) sW2[i] = Ws[i];
    }

    int w = tid >> 5, lane = tid & 31;
    int p = blockIdx.x * 8 + w;
    bool act = lane < 25;

    if (act) {   // stage this path's bow into smem (vector ld/st, aligned)
        sbow4[w][lane] = __ldcg(&g_bow[(size_t)p * 25 + lane]);
    }
    __syncthreads();

    if (act) {
        ull accA = 0ull, accB = 0ull;
        const float* bw = (const float*)sbow4[w];
        #pragma unroll 10
        for (int k = 0; k < VDIM; k += 2) {
            accA = fma2(dup2(bw[k]),     sW2[k * 25 + lane],       accA);
            accB = fma2(dup2(bw[k + 1]), sW2[(k + 1) * 25 + lane], accB);
        }
        float c0, c1, e0, e1;
        unpack2(accA, c0, c1);
        unpack2(accB, e0, e1);
        c0 += e0; c1 += e1;
        int c = 2 * lane;
        float v0 = fmaxf(c0 + __ldg(&b_enc[c]),     0.f);   // relu
        float v1 = fmaxf(c1 + __ldg(&b_enc[c + 1]), 0.f);
        atomicMaxF(&smax[c],     v0);
        atomicMaxF(&smax[c + 1], v1);
    }
    __syncthreads();

    if (tid < WAE) atomicMaxF(&g_max[RAND_DIM + tid], smax[tid]);

    // ---- fused finalize ----
    __threadfence();
    if (tid == 0) s_last = (atomicAdd(&g_done, 1) == NBLK - 1);
    __syncthreads();
    if (!s_last || w != 0) return;

    float part[CLS] = {0.f, 0.f, 0.f, 0.f};
    for (int d = lane; d < HDIM; d += 32) {
        float m = __ldcg(&g_max[d]);
        #pragma unroll
        for (int c = 0; c < CLS; c++)
            part[c] = fmaf(w_out[c * HDIM + d], m, part[c]);
    }
    #pragma unroll
    for (int off = 16; off > 0; off >>= 1) {
        #pragma unroll
        for (int c = 0; c < CLS; c++)
            part[c] += __shfl_down_sync(0xffffffffu, part[c], off);
    }
    if (lane == 0) {
        float logits[CLS], prob[CLS];
        float mx = -CUDART_INF_F;
        #pragma unroll
        for (int c = 0; c < CLS; c++) {
            logits[c] = part[c] + b_out[c];
            mx = fmaxf(mx, logits[c]);
        }
        float s = 0.f;
        #pragma unroll
        for (int c = 0; c < CLS; c++) { prob[c] = expf(logits[c] - mx); s += prob[c]; }
        #pragma unroll
        for (int c = 0; c < CLS; c++) prob[c] /= s;

        int label = 0, best = y[0];
        #pragma unroll
        for (int c = 1; c < CLS; c++) if (y[c] > best) { best = y[c]; label = c; }

        float mx2 = prob[0];
        #pragma unroll
        for (int c = 1; c < CLS; c++) mx2 = fmaxf(mx2, prob[c]);
        float s2 = 0.f;
        #pragma unroll
        for (int c = 0; c < CLS; c++) s2 += expf(prob[c] - mx2);
        float loss = -(prob[label] - (mx2 + logf(s2)));

        for (int c = 0; c < CLS && c < out_size; c++) out[c] = prob[c];
        if (out_size > CLS) out[CLS] = loss;
    }
}

// ---------------------------------------------------------------------------
extern "C" void kernel_launch(void* const* d_in, const int* in_sizes, int n_in,
                              void* d_out, int out_size) {
    const int*   x     = (const int*)  d_in[0];
    const int*   y     = (const int*)  d_in[1];
    const float* E_td  = (const float*)d_in[2];
    const float* E_wae = (const float*)d_in[3];
    const float* W_enc = (const float*)d_in[4];
    const float* b_enc = (const float*)d_in[5];
    const float* w_out = (const float*)d_in[6];
    const float* b_out = (const float*)d_in[7];
    float* out = (float*)d_out;

    convert_kernel<<<1184, 256>>>(E_td, E_wae);
    path_gather_kernel<<<NBLK, 256>>>(x);
    bow_linear_kernel<<<NBLK, 256>>>(W_enc, b_enc, w_out, b_out, y,
                                     out, out_size);
}

// round 11
// speedup vs baseline: 1.2018x; 1.0396x over previous
#include <cuda_runtime.h>
#include <cuda_fp16.h>
#include <math_constants.h>

#define VOCAB    100000
#define RAND_DIM 100
#define WAE      50
#define CLS      4
#define VDIM     100
#define NPATH    16384
#define PLEN     50
#define HDIM     150     // RAND_DIM + WAE
#define PADT     160     // table row pitch in halves: 320 B = 20 uint4, 10 sectors
#define NBLK     (NPATH / 8)

typedef unsigned long long ull;

// Fused gather table: row v = [fp16 E_td[v][0:100] | fp16 G[v][0:50] | pad 10]
// where G = E_wae @ W_enc (tensor-core precompute).
__device__ __half g_T[(size_t)VOCAB * PADT];   // 32 MB
__device__ float  g_max[HDIM];
__device__ int    g_done;

// ---------------------------------------------------------------------------
__device__ __forceinline__ __half2 asH2(unsigned u) {
    return *reinterpret_cast<__half2*>(&u);
}
__device__ __forceinline__ void atomicMaxF(float* addr, float v) {
    if (v >= 0.f) atomicMax((int*)addr, __float_as_int(v));
    else          atomicMin((unsigned int*)addr, __float_as_uint(v));
}
__device__ __forceinline__ ull packh(float a, float b, float c, float d) {
    __half2 h0 = __floats2half2_rn(a, b);
    __half2 h1 = __floats2half2_rn(c, d);
    unsigned lo = *reinterpret_cast<unsigned*>(&h0);
    unsigned hi = *reinterpret_cast<unsigned*>(&h1);
    return (ull)lo | ((ull)hi << 32);
}
__device__ __forceinline__ unsigned packh2u(float a, float b) {
    __half2 h = __floats2half2_rn(a, b);
    return *reinterpret_cast<unsigned*>(&h);
}
__device__ __forceinline__ uint4 ldcg4(const uint4* p) {
    uint4 v;
    asm volatile("ld.global.cg.v4.u32 {%0,%1,%2,%3}, [%4];"
                 : "=r"(v.x), "=r"(v.y), "=r"(v.z), "=r"(v.w) : "l"(p));
    return v;
}

// ---------------------------------------------------------------------------
// Kernel 1: stream E_td fp32 -> fp16 into table cols 0..99. Also resets
// g_max / g_done (block 0).
// ---------------------------------------------------------------------------
__global__ void __launch_bounds__(256)
convert_td_kernel(const float* __restrict__ E_td) {
    if (blockIdx.x == 0) {
        if (threadIdx.x < HDIM) g_max[threadIdx.x] = -CUDART_INF_F;
        if (threadIdx.x == 0)   g_done = 0;
    }
    const float4* A = (const float4*)E_td;   // 25 float4 per row
    ull* T = (ull*)g_T;                      // 40 ull per row
    const size_t N = (size_t)VOCAB * 25;
    size_t stride = (size_t)gridDim.x * blockDim.x;
    for (size_t i = (size_t)blockIdx.x * blockDim.x + threadIdx.x;
         i < N; i += stride) {
        float4 v = __ldcs(&A[i]);
        size_t row = i / 25, j = i % 25;
        T[row * 40 + j] = packh(v.x, v.y, v.z, v.w);
    }
}

// ---------------------------------------------------------------------------
// Kernel 2: G = E_wae @ W_enc via mma.sync m16n8k16 (f16 in, f32 accum),
// G -> fp16 table cols 100..149.
// Block = 256 threads = 8 warps; warp owns 16 vocab rows; block owns 128.
// A fragments loaded directly from global fp32 (float2 per lane + cvt);
// B (W_enc) staged in smem as [n][k] fp16, pitch 120 halves (bank-dodge).
// K = 100 padded to 112 (7 k-steps); N = 50 padded to 56 (7 n-tiles).
// ---------------------------------------------------------------------------
__device__ __forceinline__ unsigned loadA_h2(const float* E, int r, int c) {
    if (r < VOCAB && c < VDIM) {
        float2 v = *reinterpret_cast<const float2*>(E + (size_t)r * VDIM + c);
        return packh2u(v.x, v.y);
    }
    return 0u;
}

__global__ void __launch_bounds__(256)
wae_gemm_kernel(const float* __restrict__ E_wae,
                const float* __restrict__ W_enc) {
    __shared__ __half sB[56 * 120];   // [n][k], pitch 120 halves = 240 B
    int tid = threadIdx.x, w = tid >> 5, lane = tid & 31;

    for (int i = tid; i < 56 * 112; i += 256) {
        int n = i / 112, k = i % 112;
        float v = (n < WAE && k < VDIM) ? __ldg(&W_enc[k * WAE + n]) : 0.f;
        sB[n * 120 + k] = __float2half(v);
    }
    __syncthreads();

    int row0 = blockIdx.x * 128 + w * 16;
    int r0 = row0 + (lane >> 2);        // fragment row (plus +8 variant)
    int cb = (lane & 3) * 2;            // fragment col-pair base

    float acc[7][4];
    #pragma unroll
    for (int nt = 0; nt < 7; nt++)
        acc[nt][0] = acc[nt][1] = acc[nt][2] = acc[nt][3] = 0.f;

    #pragma unroll
    for (int ks = 0; ks < 7; ks++) {
        int c0 = ks * 16 + cb;
        unsigned a0 = loadA_h2(E_wae, r0,     c0);
        unsigned a1 = loadA_h2(E_wae, r0 + 8, c0);
        unsigned a2 = loadA_h2(E_wae, r0,     c0 + 8);
        unsigned a3 = loadA_h2(E_wae, r0 + 8, c0 + 8);
        int k0 = ks * 16 + cb;
        #pragma unroll
        for (int nt = 0; nt < 7; nt++) {
            int n = nt * 8 + (lane >> 2);
            unsigned b0 = *reinterpret_cast<unsigned*>(&sB[n * 120 + k0]);
            unsigned b1 = *reinterpret_cast<unsigned*>(&sB[n * 120 + k0 + 8]);
            asm volatile(
                "mma.sync.aligned.m16n8k16.row.col.f32.f16.f16.f32 "
                "{%0,%1,%2,%3}, {%4,%5,%6,%7}, {%8,%9}, {%0,%1,%2,%3};\n"
                : "+f"(acc[nt][0]), "+f"(acc[nt][1]),
                  "+f"(acc[nt][2]), "+f"(acc[nt][3])
                : "r"(a0), "r"(a1), "r"(a2), "r"(a3), "r"(b0), "r"(b1));
        }
    }

    // Store C fragments as fp16 pairs into table cols 100+col
    #pragma unroll
    for (int nt = 0; nt < 7; nt++) {
        int col = nt * 8 + cb;                       // even; pair (col, col+1)
        if (col < WAE) {
            unsigned lo = packh2u(acc[nt][0], acc[nt][1]);
            unsigned hi = packh2u(acc[nt][2], acc[nt][3]);
            if (r0 < VOCAB)
                *reinterpret_cast<unsigned*>(
                    &g_T[(size_t)r0 * PADT + RAND_DIM + col]) = lo;
            if (r0 + 8 < VOCAB)
                *reinterpret_cast<unsigned*>(
                    &g_T[(size_t)(r0 + 8) * PADT + RAND_DIM + col]) = hi;
        }
    }
}

// ---------------------------------------------------------------------------
// Kernel 3: gather + activations + max-pool + fused finalize.
// One warp per path, lanes 0..18 own 16B chunks (dims 8l..8l+7) of the
// 300B row (pitch 320B = 20 uint4, 10 sectors, <=3 cachelines per load).
// 4 tokens per body + tail, ldcg, fp16 tree.
// ---------------------------------------------------------------------------
__global__ void __launch_bounds__(256)
path_gather_kernel(const int*   __restrict__ x,
                   const float* __restrict__ b_enc,
                   const float* __restrict__ w_out,
                   const float* __restrict__ b_out,
                   const int*   __restrict__ y,
                   float* __restrict__ out, int out_size) {
    __shared__ float smax[HDIM];
    __shared__ int   s_last;
    int tid = threadIdx.x;
    if (tid < HDIM) smax[tid] = -CUDART_INF_F;
    __syncthreads();

    int w = tid >> 5, lane = tid & 31;
    int p = blockIdx.x * 8 + w;
    const int* xp = x + (size_t)p * PLEN;

    int tA = xp[lane];
    int tB = (lane < PLEN - 32) ? xp[32 + lane] : 0;

    bool act = lane < 19;                         // chunks covering dims 0..151
    const uint4* T4 = (const uint4*)g_T + lane;   // per-lane chunk base, 20/row

    float2 a0 = {0.f, 0.f}, a1 = {0.f, 0.f}, a2 = {0.f, 0.f}, a3 = {0.f, 0.f};

    #pragma unroll
    for (int t = 0; t < 48; t += 4) {
        int k0 = (t     < 32) ? __shfl_sync(0xffffffffu, tA, t)     : __shfl_sync(0xffffffffu, tB, t - 32);
        int k1 = (t + 1 < 32) ? __shfl_sync(0xffffffffu, tA, t + 1) : __shfl_sync(0xffffffffu, tB, t - 31);
        int k2 = (t + 2 < 32) ? __shfl_sync(0xffffffffu, tA, t + 2) : __shfl_sync(0xffffffffu, tB, t - 30);
        int k3 = (t + 3 < 32) ? __shfl_sync(0xffffffffu, tA, t + 3) : __shfl_sync(0xffffffffu, tB, t - 29);
        if (act) {
            uint4 v0 = ldcg4(T4 + (size_t)k0 * 20);
            uint4 v1 = ldcg4(T4 + (size_t)k1 * 20);
            uint4 v2 = ldcg4(T4 + (size_t)k2 * 20);
            uint4 v3 = ldcg4(T4 + (size_t)k3 * 20);
            __half2 s0 = __hadd2(__hadd2(asH2(v0.x), asH2(v1.x)), __hadd2(asH2(v2.x), asH2(v3.x)));
            __half2 s1 = __hadd2(__hadd2(asH2(v0.y), asH2(v1.y)), __hadd2(asH2(v2.y), asH2(v3.y)));
            __half2 s2 = __hadd2(__hadd2(asH2(v0.z), asH2(v1.z)), __hadd2(asH2(v2.z), asH2(v3.z)));
            __half2 s3 = __hadd2(__hadd2(asH2(v0.w), asH2(v1.w)), __hadd2(asH2(v2.w), asH2(v3.w)));
            float2 f;
            f = __half22float2(s0); a0.x += f.x; a0.y += f.y;
            f = __half22float2(s1); a1.x += f.x; a1.y += f.y;
            f = __half22float2(s2); a2.x += f.x; a2.y += f.y;
            f = __half22float2(s3); a3.x += f.x; a3.y += f.y;
        }
    }
    {   // tail: tokens 48, 49
        int k0 = __shfl_sync(0xffffffffu, tB, 16);
        int k1 = __shfl_sync(0xffffffffu, tB, 17);
        if (act) {
            uint4 v0 = ldcg4(T4 + (size_t)k0 * 20);
            uint4 v1 = ldcg4(T4 + (size_t)k1 * 20);
            __half2 s0 = __hadd2(asH2(v0.x), asH2(v1.x));
            __half2 s1 = __hadd2(asH2(v0.y), asH2(v1.y));
            __half2 s2 = __hadd2(asH2(v0.z), asH2(v1.z));
            __half2 s3 = __hadd2(asH2(v0.w), asH2(v1.w));
            float2 f;
            f = __half22float2(s0); a0.x += f.x; a0.y += f.y;
            f = __half22float2(s1); a1.x += f.x; a1.y += f.y;
            f = __half22float2(s2); a2.x += f.x; a2.y += f.y;
            f = __half22float2(s3); a3.x += f.x; a3.y += f.y;
        }
    }

    if (act) {
        float f[8] = {a0.x, a0.y, a1.x, a1.y, a2.x, a2.y, a3.x, a3.y};
        int d0 = lane * 8;
        #pragma unroll
        for (int j = 0; j < 8; j++) {
            int d = d0 + j;
            if (d < RAND_DIM) {                       // path_random: leaky_relu
                float v = f[j];
                v = (v > 0.f) ? v : 0.01f * v;
                atomicMaxF(&smax[d], v);
            } else if (d < HDIM) {                    // G dims: relu(sum + b)
                float v = fmaxf(f[j] + __ldg(&b_enc[d - RAND_DIM]), 0.f);
                atomicMaxF(&smax[d], v);
            }
        }
    }
    __syncthreads();

    if (tid < HDIM) atomicMaxF(&g_max[tid], smax[tid]);

    // ---- fused finalize: last block computes softmax + loss ----
    __threadfence();
    if (tid == 0) s_last = (atomicAdd(&g_done, 1) == NBLK - 1);
    __syncthreads();
    if (!s_last || w != 0) return;

    float part[CLS] = {0.f, 0.f, 0.f, 0.f};
    for (int d = lane; d < HDIM; d += 32) {
        float m = __ldcg(&g_max[d]);
        #pragma unroll
        for (int c = 0; c < CLS; c++)
            part[c] = fmaf(w_out[c * HDIM + d], m, part[c]);
    }
    #pragma unroll
    for (int off = 16; off > 0; off >>= 1) {
        #pragma unroll
        for (int c = 0; c < CLS; c++)
            part[c] += __shfl_down_sync(0xffffffffu, part[c], off);
    }
    if (lane == 0) {
        float logits[CLS], prob[CLS];
        float mx = -CUDART_INF_F;
        #pragma unroll
        for (int c = 0; c < CLS; c++) {
            logits[c] = part[c] + b_out[c];
            mx = fmaxf(mx, logits[c]);
        }
        float s = 0.f;
        #pragma unroll
        for (int c = 0; c < CLS; c++) { prob[c] = expf(logits[c] - mx); s += prob[c]; }
        #pragma unroll
        for (int c = 0; c < CLS; c++) prob[c] /= s;

        int label = 0, best = y[0];
        #pragma unroll
        for (int c = 1; c < CLS; c++) if (y[c] > best) { best = y[c]; label = c; }

        float mx2 = prob[0];
        #pragma unroll
        for (int c = 1; c < CLS; c++) mx2 = fmaxf(mx2, prob[c]);
        float s2 = 0.f;
        #pragma unroll
        for (int c = 0; c < CLS; c++) s2 += expf(prob[c] - mx2);
        float loss = -(prob[label] - (mx2 + logf(s2)));

        for (int c = 0; c < CLS && c < out_size; c++) out[c] = prob[c];
        if (out_size > CLS) out[CLS] = loss;
    }
}

// ---------------------------------------------------------------------------
extern "C" void kernel_launch(void* const* d_in, const int* in_sizes, int n_in,
                              void* d_out, int out_size) {
    const int*   x     = (const int*)  d_in[0];
    const int*   y     = (const int*)  d_in[1];
    const float* E_td  = (const float*)d_in[2];
    const float* E_wae = (const float*)d_in[3];
    const float* W_enc = (const float*)d_in[4];
    const float* b_enc = (const float*)d_in[5];
    const float* w_out = (const float*)d_in[6];
    const float* b_out = (const float*)d_in[7];
    float* out = (float*)d_out;

    convert_td_kernel<<<1184, 256>>>(E_td);
    wae_gemm_kernel<<<(VOCAB + 127) / 128, 256>>>(E_wae, W_enc);
    path_gather_kernel<<<NBLK, 256>>>(x, b_enc, w_out, b_out, y,
                                      out, out_size);
}